// round 4
// baseline (speedup 1.0000x reference)
#include <cuda_runtime.h>

#define W_IMG 1920
#define H_IMG 1080
#define HW (W_IMG * H_IMG)
#define GRID_Y 16
#define GRID_X 16
#define GRID_L 8
// one grid slice = 16*16*8*12 floats
#define GRID_ELEMS (GRID_Y * GRID_X * GRID_L * 12)

__global__ __launch_bounds__(256)
void bilateral_grid_kernel(const float* __restrict__ rgb,
                           const float* __restrict__ grids,
                           const int*   __restrict__ idx_p,
                           float* __restrict__ out)
{
    int pix = blockIdx.x * 256 + threadIdx.x;
    if (pix >= HW) return;

    int y = pix / W_IMG;
    int x = pix - y * W_IMG;

    // planar rgb loads (fully coalesced)
    float r = __ldg(rgb + pix);
    float g = __ldg(rgb + HW + pix);
    float b = __ldg(rgb + 2 * HW + pix);

    float gray = 0.299f * r + 0.587f * g + 0.114f * b;
    gray = fminf(fmaxf(gray, 0.0f), 1.0f);

    // align_corners pixel -> grid coords
    float gy = (float)y * (15.0f / 1079.0f);
    float gx = (float)x * (15.0f / 1919.0f);
    float gz = gray * 7.0f;

    float fy = floorf(gy), fx = floorf(gx), fz = floorf(gz);
    float wy = gy - fy,   wx = gx - fx,   wz = gz - fz;

    int y0 = min(max((int)fy, 0), GRID_Y - 1);
    int x0 = min(max((int)fx, 0), GRID_X - 1);
    int z0 = min(max((int)fz, 0), GRID_L - 1);
    int y1 = min(y0 + 1, GRID_Y - 1);
    int x1 = min(x0 + 1, GRID_X - 1);
    int z1 = min(z0 + 1, GRID_L - 1);

    const float* G = grids + idx_p[0] * GRID_ELEMS;

    float wys[2] = {1.0f - wy, wy};
    float wxs[2] = {1.0f - wx, wx};
    float wzs[2] = {1.0f - wz, wz};
    int   ys[2]  = {y0, y1};
    int   xs[2]  = {x0, x1};
    int   zs[2]  = {z0, z1};

    float4 a0 = make_float4(0.f, 0.f, 0.f, 0.f);
    float4 a1 = make_float4(0.f, 0.f, 0.f, 0.f);
    float4 a2 = make_float4(0.f, 0.f, 0.f, 0.f);

    #pragma unroll
    for (int iy = 0; iy < 2; iy++) {
        #pragma unroll
        for (int ix = 0; ix < 2; ix++) {
            float wyx = wys[iy] * wxs[ix];
            int base_yx = (ys[iy] * GRID_X + xs[ix]) * GRID_L;
            #pragma unroll
            for (int iz = 0; iz < 2; iz++) {
                float w = wyx * wzs[iz];
                const float4* q = (const float4*)(G + (base_yx + zs[iz]) * 12);
                float4 c0 = __ldg(q);
                float4 c1 = __ldg(q + 1);
                float4 c2 = __ldg(q + 2);
                a0.x += w * c0.x; a0.y += w * c0.y; a0.z += w * c0.z; a0.w += w * c0.w;
                a1.x += w * c1.x; a1.y += w * c1.y; a1.z += w * c1.z; a1.w += w * c1.w;
                a2.x += w * c2.x; a2.y += w * c2.y; a2.z += w * c2.z; a2.w += w * c2.w;
            }
        }
    }

    // affine_mat: out[pix*12 .. pix*12+11]
    float4* oa = (float4*)(out + (size_t)pix * 12);
    oa[0] = a0;
    oa[1] = a1;
    oa[2] = a2;

    // res_rgb: out[12*HW + pix*3 ...]
    float* orr = out + (size_t)12 * HW + (size_t)pix * 3;
    orr[0] = a0.x * r + a0.y * g + a0.z * b + a0.w;
    orr[1] = a1.x * r + a1.y * g + a1.z * b + a1.w;
    orr[2] = a2.x * r + a2.y * g + a2.z * b + a2.w;
}

extern "C" void kernel_launch(void* const* d_in, const int* in_sizes, int n_in,
                              void* d_out, int out_size)
{
    const float* rgb   = (const float*)d_in[0];
    const float* grids = (const float*)d_in[1];
    const int*   idx   = (const int*)d_in[2];
    float* out = (float*)d_out;

    int blocks = (HW + 255) / 256;
    bilateral_grid_kernel<<<blocks, 256>>>(rgb, grids, idx, out);
}

// round 6
// speedup vs baseline: 1.1567x; 1.1567x over previous
#include <cuda_runtime.h>

#define W_IMG 1920
#define H_IMG 1080
#define HW (W_IMG * H_IMG)
#define GRID_Y 16
#define GRID_X 16
#define GRID_L 8
#define GRID_ELEMS (GRID_Y * GRID_X * GRID_L * 12)

// Block: 128 threads = 128 consecutive pixels of ONE image row.
// gridDim = (1920/128 = 15, 1080).
// y-interpolation (wy, y0, y1) is uniform per row -> pre-blend the two y-levels
// of the (at most 3) grid x-columns the block touches into a smem slab:
//   slab[xcol 0..2][z 0..7][12 coeffs]  (288 floats, 1.2 KB)
// Each pixel then does a 4-corner (x,z) bilinear from smem: 12 LDS.128 instead
// of 24 scattered LDG.128. z-stride is 48B, so the 8 z-slots tile the 32 banks
// exactly -> near conflict-free LDS.

__global__ __launch_bounds__(128)
void bilateral_grid_kernel(const float* __restrict__ rgb,
                           const float* __restrict__ grids,
                           const int*   __restrict__ idx_p,
                           float* __restrict__ out)
{
    __shared__ __align__(16) float slab[3 * GRID_L * 12];   // 288 floats

    const int tid = threadIdx.x;
    const int y   = blockIdx.y;
    const int x   = blockIdx.x * 128 + tid;
    const int pix = y * W_IMG + x;

    // ---- per-row y interpolation setup (uniform across block) ----
    float gy = (float)y * (15.0f / 1079.0f);
    float fy = floorf(gy);
    float wy = gy - fy;
    int y0 = (int)fy;
    if (y0 > GRID_Y - 1) y0 = GRID_Y - 1;
    int y1 = min(y0 + 1, GRID_Y - 1);

    // ---- block's base grid x-column ----
    float gx_first = (float)(blockIdx.x * 128) * (15.0f / 1919.0f);
    int xc0 = (int)floorf(gx_first);

    const float* G = grids + idx_p[0] * GRID_ELEMS;

    // ---- build y-blended slab: 3 xcols x 8 z x 12 coeffs ----
    #pragma unroll
    for (int i = tid; i < 3 * GRID_L * 12; i += 128) {
        int xcol = i / (GRID_L * 12);
        int rem  = i - xcol * (GRID_L * 12);          // z*12 + q
        int gxc  = min(xc0 + xcol, GRID_X - 1);
        int base = ((y0 * GRID_X + gxc) * GRID_L) * 12 + rem;
        int base1 = ((y1 * GRID_X + gxc) * GRID_L) * 12 + rem;
        float a = __ldg(G + base);
        float b = __ldg(G + base1);
        slab[i] = fmaf(wy, b - a, a);                 // (1-wy)*a + wy*b
    }
    __syncthreads();

    // ---- per-pixel ----
    float r = __ldg(rgb + pix);
    float g = __ldg(rgb + HW + pix);
    float b = __ldg(rgb + 2 * HW + pix);

    float gray = 0.299f * r + 0.587f * g + 0.114f * b;
    gray = fminf(fmaxf(gray, 0.0f), 1.0f);

    float gz = gray * 7.0f;
    float fz = floorf(gz);
    float wz = gz - fz;
    int z0 = (int)fz;
    if (z0 > GRID_L - 1) z0 = GRID_L - 1;
    int z1 = min(z0 + 1, GRID_L - 1);

    float gxp = (float)x * (15.0f / 1919.0f);
    float fx = floorf(gxp);
    float wx = gxp - fx;
    int x0  = (int)fx;
    int lx0 = x0 - xc0;                         // 0 or 1
    int lx1 = min(x0 + 1, GRID_X - 1) - xc0;    // lx0 .. lx0+1, <= 2

    float w00 = (1.0f - wx) * (1.0f - wz);
    float w01 = (1.0f - wx) * wz;
    float w10 = wx * (1.0f - wz);
    float w11 = wx * wz;

    const float4* c00 = (const float4*)(slab + (lx0 * GRID_L + z0) * 12);
    const float4* c01 = (const float4*)(slab + (lx0 * GRID_L + z1) * 12);
    const float4* c10 = (const float4*)(slab + (lx1 * GRID_L + z0) * 12);
    const float4* c11 = (const float4*)(slab + (lx1 * GRID_L + z1) * 12);

    float4 a0, a1, a2;
    {
        float4 p00 = c00[0], p01 = c01[0], p10 = c10[0], p11 = c11[0];
        a0.x = w00 * p00.x + w01 * p01.x + w10 * p10.x + w11 * p11.x;
        a0.y = w00 * p00.y + w01 * p01.y + w10 * p10.y + w11 * p11.y;
        a0.z = w00 * p00.z + w01 * p01.z + w10 * p10.z + w11 * p11.z;
        a0.w = w00 * p00.w + w01 * p01.w + w10 * p10.w + w11 * p11.w;
    }
    {
        float4 p00 = c00[1], p01 = c01[1], p10 = c10[1], p11 = c11[1];
        a1.x = w00 * p00.x + w01 * p01.x + w10 * p10.x + w11 * p11.x;
        a1.y = w00 * p00.y + w01 * p01.y + w10 * p10.y + w11 * p11.y;
        a1.z = w00 * p00.z + w01 * p01.z + w10 * p10.z + w11 * p11.z;
        a1.w = w00 * p00.w + w01 * p01.w + w10 * p10.w + w11 * p11.w;
    }
    {
        float4 p00 = c00[2], p01 = c01[2], p10 = c10[2], p11 = c11[2];
        a2.x = w00 * p00.x + w01 * p01.x + w10 * p10.x + w11 * p11.x;
        a2.y = w00 * p00.y + w01 * p01.y + w10 * p10.y + w11 * p11.y;
        a2.z = w00 * p00.z + w01 * p01.z + w10 * p10.z + w11 * p11.z;
        a2.w = w00 * p00.w + w01 * p01.w + w10 * p10.w + w11 * p11.w;
    }

    // affine_mat: out[pix*12 .. pix*12+11]
    float4* oa = (float4*)(out + (size_t)pix * 12);
    oa[0] = a0;
    oa[1] = a1;
    oa[2] = a2;

    // res_rgb: out[12*HW + pix*3 ...]
    float* orr = out + (size_t)12 * HW + (size_t)pix * 3;
    orr[0] = a0.x * r + a0.y * g + a0.z * b + a0.w;
    orr[1] = a1.x * r + a1.y * g + a1.z * b + a1.w;
    orr[2] = a2.x * r + a2.y * g + a2.z * b + a2.w;
}

extern "C" void kernel_launch(void* const* d_in, const int* in_sizes, int n_in,
                              void* d_out, int out_size)
{
    const float* rgb   = (const float*)d_in[0];
    const float* grids = (const float*)d_in[1];
    const int*   idx   = (const int*)d_in[2];
    float* out = (float*)d_out;

    dim3 grid(W_IMG / 128, H_IMG);
    bilateral_grid_kernel<<<grid, 128>>>(rgb, grids, idx, out);
}